// round 8
// baseline (speedup 1.0000x reference)
#include <cuda_runtime.h>
#include <cstdint>
#include <cstddef>

#define S_LEN 2048
#define DIM   4096
#define NH    32
#define HD    128
#define BATCH 2
#define MTOT  (BATCH*S_LEN)

typedef unsigned long long u64;

__device__ __forceinline__ u64 pk2(float x, float y){
    u64 r; asm("mov.b64 %0, {%1,%2};" : "=l"(r) : "f"(x), "f"(y)); return r;
}
__device__ __forceinline__ float2 upk2(u64 v){
    float2 r; asm("mov.b64 {%0,%1}, %2;" : "=f"(r.x), "=f"(r.y) : "l"(v)); return r;
}
__device__ __forceinline__ void fma2(u64 &d, u64 a, u64 b){
    asm("fma.rn.f32x2 %0, %1, %2, %0;" : "+l"(d) : "l"(a), "l"(b));
}
__device__ __forceinline__ u64 mul2(u64 a, u64 b){
    u64 r; asm("mul.rn.f32x2 %0, %1, %2;" : "=l"(r) : "l"(a), "l"(b)); return r;
}

__device__ float g_q[(size_t)MTOT*DIM];
__device__ float g_k[(size_t)MTOT*DIM];
__device__ float g_v[(size_t)MTOT*DIM];
__device__ float g_att[(size_t)MTOT*DIM];

// ============ GEMM: C[M,N] = A[M,K] * B[N,K]^T, M=N=K=4096 ============
__global__ __launch_bounds__(256, 2)
void gemm_nt128(const float* __restrict__ A, const float* __restrict__ Bm,
                float* __restrict__ C)
{
    const int K = DIM, N = DIM;
    __shared__ float As[16][132];   // [k][m]
    __shared__ float Bs[16][132];   // [k][n]

    const int tid  = threadIdx.x;
    const int brow = blockIdx.y, bcol = blockIdx.x;
    const float* Ap = A  + (size_t)brow * 128 * K;
    const float* Bp = Bm + (size_t)bcol * 128 * K;

    const int lr = tid >> 2;
    const int lc = (tid & 3) << 2;

    const int warp = tid >> 5, lane = tid & 31;
    const int wm = warp >> 1, wn = warp & 1;
    const int r0 = wm * 32 + (lane >> 3) * 4;
    const int c0 = wn * 64 + (lane & 7) * 4;

    u64 acc[8][4];
    #pragma unroll
    for (int i = 0; i < 8; i++)
        #pragma unroll
        for (int j = 0; j < 4; j++) acc[i][j] = 0ull;

    float4 pa[2], pb[2];
    pa[0] = *(const float4*)(Ap + (size_t)lr        * K + lc);
    pa[1] = *(const float4*)(Ap + (size_t)(lr + 64) * K + lc);
    pb[0] = *(const float4*)(Bp + (size_t)lr        * K + lc);
    pb[1] = *(const float4*)(Bp + (size_t)(lr + 64) * K + lc);

    const int ktiles = K >> 4;
    for (int kt = 0; kt < ktiles; kt++) {
        __syncthreads();
        #pragma unroll
        for (int p = 0; p < 2; p++) {
            const int rr = lr + p * 64;
            As[lc + 0][rr] = pa[p].x;  As[lc + 1][rr] = pa[p].y;
            As[lc + 2][rr] = pa[p].z;  As[lc + 3][rr] = pa[p].w;
            Bs[lc + 0][rr] = pb[p].x;  Bs[lc + 1][rr] = pb[p].y;
            Bs[lc + 2][rr] = pb[p].z;  Bs[lc + 3][rr] = pb[p].w;
        }
        __syncthreads();

        if (kt + 1 < ktiles) {
            const float* An = Ap + (size_t)(kt + 1) * 16;
            const float* Bn = Bp + (size_t)(kt + 1) * 16;
            pa[0] = *(const float4*)(An + (size_t)lr        * K + lc);
            pa[1] = *(const float4*)(An + (size_t)(lr + 64) * K + lc);
            pb[0] = *(const float4*)(Bn + (size_t)lr        * K + lc);
            pb[1] = *(const float4*)(Bn + (size_t)(lr + 64) * K + lc);
        }

        #pragma unroll
        for (int k = 0; k < 16; k++) {
            float4 a0 = *(const float4*)&As[k][r0];
            float4 a1 = *(const float4*)&As[k][r0 + 16];
            float4 b0 = *(const float4*)&Bs[k][c0];
            float4 b1 = *(const float4*)&Bs[k][c0 + 32];
            u64 bp4[4] = { pk2(b0.x, b0.y), pk2(b0.z, b0.w),
                           pk2(b1.x, b1.y), pk2(b1.z, b1.w) };
            float av[8] = { a0.x, a0.y, a0.z, a0.w, a1.x, a1.y, a1.z, a1.w };
            #pragma unroll
            for (int i = 0; i < 8; i++) {
                u64 ad = pk2(av[i], av[i]);
                #pragma unroll
                for (int j = 0; j < 4; j++) fma2(acc[i][j], ad, bp4[j]);
            }
        }
    }

    #pragma unroll
    for (int i = 0; i < 8; i++) {
        const int row = brow * 128 + ((i < 4) ? (r0 + i) : (r0 + 16 + (i - 4)));
        float* Cr = C + (size_t)row * N + (size_t)bcol * 128;
        float2 x0 = upk2(acc[i][0]), x1 = upk2(acc[i][1]);
        float2 x2 = upk2(acc[i][2]), x3 = upk2(acc[i][3]);
        *(float4*)(Cr + c0)      = make_float4(x0.x, x0.y, x1.x, x1.y);
        *(float4*)(Cr + c0 + 32) = make_float4(x2.x, x2.y, x3.x, x3.y);
    }
}

// ============ RoPE in-place on Q and K ============
__global__ void rope_kernel(float* __restrict__ q, float* __restrict__ k,
                            const float* __restrict__ cosT, const float* __restrict__ sinT)
{
    const int idx = blockIdx.x * blockDim.x + threadIdx.x;  // MTOT*NH*64 threads
    const int d2 = idx & 63;
    const int t  = idx >> 6;
    const int hh = t & (NH - 1);
    const int bs = t >> 5;
    const int s  = bs & (S_LEN - 1);

    const float c  = cosT[(s << 6) + d2];
    const float sn = sinT[(s << 6) + d2];
    const size_t base = ((size_t)bs << 12) + ((size_t)hh << 7) + ((size_t)d2 << 1);

    float2 qv = *(float2*)(q + base);
    float2 kv = *(float2*)(k + base);
    float2 qo, ko;
    qo.x = qv.x * c - qv.y * sn;  qo.y = qv.x * sn + qv.y * c;
    ko.x = kv.x * c - kv.y * sn;  ko.y = kv.x * sn + kv.y * c;
    *(float2*)(q + base) = qo;
    *(float2*)(k + base) = ko;
}

// ============ Flash attention (causal). CTA = (64 q rows, head, batch) ============
__global__ __launch_bounds__(256, 1)
void flash_attn(const float* __restrict__ Qg, const float* __restrict__ Kg,
                const float* __restrict__ Vg, float* __restrict__ Og)
{
    extern __shared__ float sm[];
    float* Qt   = sm;                 // [128][68] transposed, pre-scaled
    float* Kt   = Qt + 128 * 68;      // [128][68] transposed
    float* Vs   = Kt + 128 * 68;      // [64][132] row-major
    float* Ps   = Vs + 64 * 132;      // [64][68]
    float* rowM = Ps + 64 * 68;
    float* rowL = rowM + 64;
    float* rowS = rowL + 64;

    const int tid = threadIdx.x;
    const int qi = blockIdx.x, h = blockIdx.y, b = blockIdx.z;
    const int q0 = qi * 64;

    const int ldr = tid >> 2;
    const int ldc = (tid & 3) * 32;

    {
        const float qs = 0.08838834764831845f;   // 1/sqrt(128)
        const float* src = Qg + ((size_t)(b * S_LEN + q0 + ldr)) * DIM + h * HD + ldc;
        #pragma unroll
        for (int j = 0; j < 8; j++) {
            float4 v = *(const float4*)(src + j * 4);
            const int c = ldc + j * 4;
            Qt[(c + 0) * 68 + ldr] = v.x * qs;
            Qt[(c + 1) * 68 + ldr] = v.y * qs;
            Qt[(c + 2) * 68 + ldr] = v.z * qs;
            Qt[(c + 3) * 68 + ldr] = v.w * qs;
        }
    }
    if (tid < 64) { rowM[tid] = -1e30f; rowL[tid] = 0.0f; }

    u64 accO[4][4];
    #pragma unroll
    for (int i = 0; i < 4; i++)
        #pragma unroll
        for (int j = 0; j < 4; j++) accO[i][j] = 0ull;

    const int warp = tid >> 5, lane = tid & 31;
    const int wm = warp >> 1, wn = warp & 1;
    const int sr0 = wm * 16 + (lane >> 3) * 4;
    const int sc0 = wn * 32 + (lane & 7) * 4;
    const int tr2 = tid >> 4, tc2 = tid & 15;
    const int seg = tid & 3, srow = tid >> 2;

    for (int kt = 0; kt <= qi; kt++) {
        __syncthreads();
        {
            const size_t rb = ((size_t)(b * S_LEN + kt * 64 + ldr)) * DIM + h * HD + ldc;
            const float* ksrc = Kg + rb;
            const float* vsrc = Vg + rb;
            #pragma unroll
            for (int j = 0; j < 8; j++) {
                float4 kv = *(const float4*)(ksrc + j * 4);
                const int c = ldc + j * 4;
                Kt[(c + 0) * 68 + ldr] = kv.x;
                Kt[(c + 1) * 68 + ldr] = kv.y;
                Kt[(c + 2) * 68 + ldr] = kv.z;
                Kt[(c + 3) * 68 + ldr] = kv.w;
                *(float4*)(Vs + ldr * 132 + c) = *(const float4*)(vsrc + j * 4);
            }
        }
        __syncthreads();

        // S = Q K^T
        u64 acc2[4][4];
        #pragma unroll
        for (int i = 0; i < 4; i++)
            #pragma unroll
            for (int j = 0; j < 4; j++) acc2[i][j] = 0ull;

        #pragma unroll 4
        for (int d2 = 0; d2 < 64; d2++) {
            const float* qr0 = Qt + (2 * d2) * 68;
            const float* kr0 = Kt + (2 * d2) * 68;
            float4 qa = *(const float4*)(qr0 + sr0);
            float4 qb = *(const float4*)(qr0 + 68 + sr0);
            float4 ka = *(const float4*)(kr0 + sc0);
            float4 kb = *(const float4*)(kr0 + 68 + sc0);
            u64 qp[4] = { pk2(qa.x, qb.x), pk2(qa.y, qb.y), pk2(qa.z, qb.z), pk2(qa.w, qb.w) };
            u64 kp[4] = { pk2(ka.x, kb.x), pk2(ka.y, kb.y), pk2(ka.z, kb.z), pk2(ka.w, kb.w) };
            #pragma unroll
            for (int i = 0; i < 4; i++)
                #pragma unroll
                for (int j = 0; j < 4; j++) fma2(acc2[i][j], qp[i], kp[j]);
        }

        const bool diag = (kt == qi);
        #pragma unroll
        for (int i = 0; i < 4; i++) {
            float sv[4];
            #pragma unroll
            for (int j = 0; j < 4; j++) {
                float2 p = upk2(acc2[i][j]);
                float s = p.x + p.y;
                if (diag && (sc0 + j) > (sr0 + i)) s = -1e30f;
                sv[j] = s;
            }
            *(float4*)(Ps + (sr0 + i) * 68 + sc0) = make_float4(sv[0], sv[1], sv[2], sv[3]);
        }
        __syncthreads();

        // online softmax: 4 lanes per row, 16 cols each
        {
            float* prow = Ps + srow * 68 + seg * 16;
            float xv[16];
            #pragma unroll
            for (int j = 0; j < 4; j++) {
                float4 v = *(const float4*)(prow + j * 4);
                xv[j*4+0] = v.x; xv[j*4+1] = v.y; xv[j*4+2] = v.z; xv[j*4+3] = v.w;
            }
            float mloc = -1e30f;
            #pragma unroll
            for (int j = 0; j < 16; j++) mloc = fmaxf(mloc, xv[j]);
            mloc = fmaxf(mloc, __shfl_xor_sync(0xffffffffu, mloc, 1));
            mloc = fmaxf(mloc, __shfl_xor_sync(0xffffffffu, mloc, 2));

            const float mold = rowM[srow];
            const float mnew = fmaxf(mold, mloc);
            const float fac  = __expf(mold - mnew);

            float ssum = 0.0f;
            #pragma unroll
            for (int j = 0; j < 16; j++) { xv[j] = __expf(xv[j] - mnew); ssum += xv[j]; }
            #pragma unroll
            for (int j = 0; j < 4; j++)
                *(float4*)(prow + j * 4) = make_float4(xv[j*4+0], xv[j*4+1], xv[j*4+2], xv[j*4+3]);

            ssum += __shfl_xor_sync(0xffffffffu, ssum, 1);
            ssum += __shfl_xor_sync(0xffffffffu, ssum, 2);
            if (seg == 0) {
                rowM[srow] = mnew;
                rowL[srow] = rowL[srow] * fac + ssum;
                rowS[srow] = fac;
            }
        }
        __syncthreads();

        // O = O*fac + P*V
        #pragma unroll
        for (int i = 0; i < 4; i++) {
            const float f = rowS[tr2 * 4 + i];
            const u64 fd = pk2(f, f);
            #pragma unroll
            for (int j = 0; j < 4; j++) accO[i][j] = mul2(accO[i][j], fd);
        }
        #pragma unroll 4
        for (int k = 0; k < 64; k++) {
            float4 v0 = *(const float4*)(Vs + k * 132 + tc2 * 4);
            float4 v1 = *(const float4*)(Vs + k * 132 + 64 + tc2 * 4);
            u64 vb[4] = { pk2(v0.x, v0.y), pk2(v0.z, v0.w),
                          pk2(v1.x, v1.y), pk2(v1.z, v1.w) };
            #pragma unroll
            for (int i = 0; i < 4; i++) {
                const float p = Ps[(tr2 * 4 + i) * 68 + k];
                const u64 pd = pk2(p, p);
                #pragma unroll
                for (int j = 0; j < 4; j++) fma2(accO[i][j], pd, vb[j]);
            }
        }
    }

    #pragma unroll
    for (int i = 0; i < 4; i++) {
        const int r = tr2 * 4 + i;
        const float inv = 1.0f / rowL[r];
        const u64 iv = pk2(inv, inv);
        float2 a0 = upk2(mul2(accO[i][0], iv));
        float2 a1 = upk2(mul2(accO[i][1], iv));
        float2 a2 = upk2(mul2(accO[i][2], iv));
        float2 a3 = upk2(mul2(accO[i][3], iv));
        float* dst = Og + ((size_t)(b * S_LEN + q0 + r)) * DIM + h * HD;
        *(float4*)(dst + tc2 * 4)      = make_float4(a0.x, a0.y, a1.x, a1.y);
        *(float4*)(dst + 64 + tc2 * 4) = make_float4(a2.x, a2.y, a3.x, a3.y);
    }
}

#define ATT_SMEM_BYTES ((128*68*2 + 64*132 + 64*68 + 192) * 4)

extern "C" void kernel_launch(void* const* d_in, const int* in_sizes, int n_in,
                              void* d_out, int out_size)
{
    const float* x  = (const float*)d_in[0];
    const float* wq = (const float*)d_in[1];
    const float* wk = (const float*)d_in[2];
    const float* wv = (const float*)d_in[3];
    const float* wo = (const float*)d_in[4];
    const float* fc = (const float*)d_in[5];
    const float* fs = (const float*)d_in[6];
    float* out = (float*)d_out;

    float *q, *k, *v, *att;
    cudaGetSymbolAddress((void**)&q,   g_q);
    cudaGetSymbolAddress((void**)&k,   g_k);
    cudaGetSymbolAddress((void**)&v,   g_v);
    cudaGetSymbolAddress((void**)&att, g_att);

    cudaFuncSetAttribute(flash_attn, cudaFuncAttributeMaxDynamicSharedMemorySize,
                         ATT_SMEM_BYTES);

    dim3 gt(32, 32);
    gemm_nt128<<<gt, 256>>>(x, wq, q);
    gemm_nt128<<<gt, 256>>>(x, wk, k);
    gemm_nt128<<<gt, 256>>>(x, wv, v);

    rope_kernel<<<(MTOT * NH * 64) / 256, 256>>>(q, k, fc, fs);

    dim3 ga(S_LEN / 64, NH, BATCH);
    flash_attn<<<ga, 256, ATT_SMEM_BYTES>>>(q, k, v, att);

    gemm_nt128<<<gt, 256>>>(att, wo, out);
}

// round 10
// speedup vs baseline: 1.6143x; 1.6143x over previous
#include <cuda_runtime.h>
#include <cuda_bf16.h>
#include <cstdint>
#include <cstddef>

#define S_LEN 2048
#define DIM   4096
#define NH    32
#define HD    128
#define BATCH 2
#define MTOT  (BATCH*S_LEN)

typedef unsigned long long u64;
typedef unsigned int u32;

// ---------------- f32x2 helpers (flash attention) ----------------
__device__ __forceinline__ u64 pk2(float x, float y){
    u64 r; asm("mov.b64 %0, {%1,%2};" : "=l"(r) : "f"(x), "f"(y)); return r;
}
__device__ __forceinline__ float2 upk2(u64 v){
    float2 r; asm("mov.b64 {%0,%1}, %2;" : "=f"(r.x), "=f"(r.y) : "l"(v)); return r;
}
__device__ __forceinline__ void fma2(u64 &d, u64 a, u64 b){
    asm("fma.rn.f32x2 %0, %1, %2, %0;" : "+l"(d) : "l"(a), "l"(b));
}
__device__ __forceinline__ u64 mul2(u64 a, u64 b){
    u64 r; asm("mul.rn.f32x2 %0, %1, %2;" : "=l"(r) : "l"(a), "l"(b)); return r;
}

// ---------------- HMMA helpers (baseline PTX, legal on sm_103) ----------------
__device__ __forceinline__ u32 smem_u32(const void* p){
    u32 a; asm("{ .reg .u64 t; cvta.to.shared.u64 t, %1; cvt.u32.u64 %0, t; }" : "=r"(a) : "l"(p));
    return a;
}
__device__ __forceinline__ void mma16816(float* c, const u32* a, const u32* b){
    asm volatile("mma.sync.aligned.m16n8k16.row.col.f32.bf16.bf16.f32 "
        "{%0,%1,%2,%3}, {%4,%5,%6,%7}, {%8,%9}, {%0,%1,%2,%3};"
        : "+f"(c[0]), "+f"(c[1]), "+f"(c[2]), "+f"(c[3])
        : "r"(a[0]), "r"(a[1]), "r"(a[2]), "r"(a[3]), "r"(b[0]), "r"(b[1]));
}
__device__ __forceinline__ void ldsm4(u32* r, u32 addr){
    asm volatile("ldmatrix.sync.aligned.m8n8.x4.shared.b16 {%0,%1,%2,%3}, [%4];"
        : "=r"(r[0]), "=r"(r[1]), "=r"(r[2]), "=r"(r[3]) : "r"(addr));
}
__device__ __forceinline__ void cpa16(u32 dst, const void* src){
    asm volatile("cp.async.cg.shared.global [%0], [%1], 16;" :: "r"(dst), "l"(src) : "memory");
}

// ---------------- scratch ----------------
__device__ float g_q[(size_t)MTOT*DIM];
__device__ float g_k[(size_t)MTOT*DIM];
__device__ float g_v[(size_t)MTOT*DIM];
__device__ float g_att[(size_t)MTOT*DIM];
__device__ __nv_bfloat16 g_xh[(size_t)MTOT*DIM],  g_xl[(size_t)MTOT*DIM];
__device__ __nv_bfloat16 g_wqh[(size_t)DIM*DIM], g_wql[(size_t)DIM*DIM];
__device__ __nv_bfloat16 g_wkh[(size_t)DIM*DIM], g_wkl[(size_t)DIM*DIM];
__device__ __nv_bfloat16 g_wvh[(size_t)DIM*DIM], g_wvl[(size_t)DIM*DIM];
__device__ __nv_bfloat16 g_woh[(size_t)DIM*DIM], g_wol[(size_t)DIM*DIM];
__device__ __nv_bfloat16 g_ah[(size_t)MTOT*DIM], g_al[(size_t)MTOT*DIM];

// ============ fp32 -> (bf16 hi, bf16 lo) split ============
__global__ __launch_bounds__(256)
void split_bf16(const float* __restrict__ s,
                __nv_bfloat16* __restrict__ h, __nv_bfloat16* __restrict__ l)
{
    const size_t i = ((size_t)blockIdx.x * 256 + threadIdx.x) * 4;
    float4 v = *(const float4*)(s + i);
    float xs[4] = { v.x, v.y, v.z, v.w };
    unsigned short hs[4], ls[4];
    #pragma unroll
    for (int j = 0; j < 4; j++) {
        __nv_bfloat16 hb = __float2bfloat16_rn(xs[j]);
        float res = xs[j] - __bfloat162float(hb);
        __nv_bfloat16 lb = __float2bfloat16_rn(res);
        hs[j] = __bfloat16_as_ushort(hb);
        ls[j] = __bfloat16_as_ushort(lb);
    }
    uint2 H, L;
    H.x = (u32)hs[0] | ((u32)hs[1] << 16);  H.y = (u32)hs[2] | ((u32)hs[3] << 16);
    L.x = (u32)ls[0] | ((u32)ls[1] << 16);  L.y = (u32)ls[2] | ((u32)ls[3] << 16);
    *(uint2*)(h + i) = H;
    *(uint2*)(l + i) = L;
}

// ============ 3xBF16 HMMA GEMM: C[M,N] = A[M,K]*B[N,K]^T ============
// 128x128 tile, BK=32, 256 threads (8 warps 4x2, warp tile 32x64), cp.async x2 stages.
// Stage layout: Ah[128][40] Al Bh Bl (10240 B each) -> 40960 B/stage, 2 stages.
#define LDT    40                 // padded row stride (bf16 elems) -> 80 B
#define ARR_B  (128*LDT*2)        // 10240 bytes per operand tile
#define STAGE  (4*ARR_B)          // 40960
#define GEMM_SMEM (2*STAGE)

__global__ __launch_bounds__(256, 2)
void gemm_hmma3(const __nv_bfloat16* __restrict__ Ah, const __nv_bfloat16* __restrict__ Al,
                const __nv_bfloat16* __restrict__ Bh, const __nv_bfloat16* __restrict__ Bl,
                float* __restrict__ C)
{
    extern __shared__ char dsm[];
    const u32 sbase = smem_u32(dsm);

    const int tid  = threadIdx.x;
    const int brow = blockIdx.y, bcol = blockIdx.x;
    const int warp = tid >> 5, lane = tid & 31;
    const int wm = warp >> 1, wn = warp & 1;    // 4 x 2 warps

    float acc[2][8][4];
    #pragma unroll
    for (int i = 0; i < 2; i++)
        #pragma unroll
        for (int j = 0; j < 8; j++)
            #pragma unroll
            for (int q = 0; q < 4; q++) acc[i][j][q] = 0.0f;

    // per-thread load mapping: 2 chunks x 4 arrays, 16B each
    const int idx0 = tid, idx1 = tid + 256;
    const int row0 = idx0 >> 2, c80 = (idx0 & 3) * 8;
    const int row1 = idx1 >> 2, c81 = (idx1 & 3) * 8;

    #define PREFETCH(kt) do {                                                        \
        const u32 sb = sbase + ((kt) & 1) * STAGE;                                   \
        const size_t ga0 = (size_t)(brow*128 + row0)*DIM + (size_t)(kt)*32 + c80;    \
        const size_t gb0 = (size_t)(bcol*128 + row0)*DIM + (size_t)(kt)*32 + c80;    \
        const size_t ga1 = (size_t)(brow*128 + row1)*DIM + (size_t)(kt)*32 + c81;    \
        const size_t gb1 = (size_t)(bcol*128 + row1)*DIM + (size_t)(kt)*32 + c81;    \
        const u32 s0 = sb + (u32)(row0*80 + c80*2);                                  \
        const u32 s1 = sb + (u32)(row1*80 + c81*2);                                  \
        cpa16(s0,             Ah + ga0);  cpa16(s1,             Ah + ga1);           \
        cpa16(s0 + ARR_B,     Al + ga0);  cpa16(s1 + ARR_B,     Al + ga1);           \
        cpa16(s0 + 2*ARR_B,   Bh + gb0);  cpa16(s1 + 2*ARR_B,   Bh + gb1);           \
        cpa16(s0 + 3*ARR_B,   Bl + gb0);  cpa16(s1 + 3*ARR_B,   Bl + gb1);           \
        asm volatile("cp.async.commit_group;" ::: "memory");                         \
    } while (0)

    PREFETCH(0);

    // ldmatrix address components (constant across iterations)
    const int a_r = (lane & 15);               // + mf*16 + wm*32
    const int a_c = (lane >> 4) * 8;           // + k0
    const int b_r = (lane & 7) + ((lane >> 4) * 8);   // + nf2*16 + wn*64
    const int b_c = ((lane >> 3) & 1) * 8;     // + k0

    #pragma unroll 1
    for (int kt = 0; kt < 128; kt++) {
        if (kt + 1 < 128) {
            PREFETCH(kt + 1);
            asm volatile("cp.async.wait_group 1;" ::: "memory");
        } else {
            asm volatile("cp.async.wait_group 0;" ::: "memory");
        }
        __syncthreads();

        const u32 aB  = sbase + (kt & 1) * STAGE;
        const u32 alB = aB + ARR_B;
        const u32 bhB = aB + 2*ARR_B;
        const u32 blB = aB + 3*ARR_B;

        #pragma unroll
        for (int ks = 0; ks < 2; ks++) {
            const int k0 = ks * 16;
            u32 ahf[2][4], alf[2][4];
            #pragma unroll
            for (int mf = 0; mf < 2; mf++) {
                const u32 off = (u32)((wm*32 + mf*16 + a_r) * 80 + (k0 + a_c) * 2);
                ldsm4(ahf[mf], aB  + off);
                ldsm4(alf[mf], alB + off);
            }
            #pragma unroll
            for (int nf2 = 0; nf2 < 4; nf2++) {
                const u32 offb = (u32)((wn*64 + nf2*16 + b_r) * 80 + (k0 + b_c) * 2);
                u32 bhf[4], blf[4];
                ldsm4(bhf, bhB + offb);
                ldsm4(blf, blB + offb);
                #pragma unroll
                for (int mf = 0; mf < 2; mf++) {
                    #pragma unroll
                    for (int h = 0; h < 2; h++) {
                        float* c = acc[mf][nf2*2 + h];
                        mma16816(c, ahf[mf], bhf + 2*h);
                        mma16816(c, alf[mf], bhf + 2*h);
                        mma16816(c, ahf[mf], blf + 2*h);
                    }
                }
            }
        }
        __syncthreads();
    }

    // epilogue
    #pragma unroll
    for (int mf = 0; mf < 2; mf++) {
        #pragma unroll
        for (int nf = 0; nf < 8; nf++) {
            const int r0 = brow*128 + wm*32 + mf*16 + (lane >> 2);
            const int c0 = bcol*128 + wn*64 + nf*8 + (lane & 3)*2;
            float* p = C + (size_t)r0 * DIM + c0;
            *(float2*)p             = make_float2(acc[mf][nf][0], acc[mf][nf][1]);
            *(float2*)(p + 8*DIM)   = make_float2(acc[mf][nf][2], acc[mf][nf][3]);
        }
    }
    #undef PREFETCH
}

// ============ RoPE in-place on Q and K ============
__global__ void rope_kernel(float* __restrict__ q, float* __restrict__ k,
                            const float* __restrict__ cosT, const float* __restrict__ sinT)
{
    const int idx = blockIdx.x * blockDim.x + threadIdx.x;
    const int d2 = idx & 63;
    const int t  = idx >> 6;
    const int hh = t & (NH - 1);
    const int bs = t >> 5;
    const int s  = bs & (S_LEN - 1);

    const float c  = cosT[(s << 6) + d2];
    const float sn = sinT[(s << 6) + d2];
    const size_t base = ((size_t)bs << 12) + ((size_t)hh << 7) + ((size_t)d2 << 1);

    float2 qv = *(float2*)(q + base);
    float2 kv = *(float2*)(k + base);
    float2 qo, ko;
    qo.x = qv.x * c - qv.y * sn;  qo.y = qv.x * sn + qv.y * c;
    ko.x = kv.x * c - kv.y * sn;  ko.y = kv.x * sn + kv.y * c;
    *(float2*)(q + base) = qo;
    *(float2*)(k + base) = ko;
}

// ============ Flash attention (causal), unchanged from R8 (passing) ============
__global__ __launch_bounds__(256, 1)
void flash_attn(const float* __restrict__ Qg, const float* __restrict__ Kg,
                const float* __restrict__ Vg, float* __restrict__ Og)
{
    extern __shared__ float sm[];
    float* Qt   = sm;
    float* Kt   = Qt + 128 * 68;
    float* Vs   = Kt + 128 * 68;
    float* Ps   = Vs + 64 * 132;
    float* rowM = Ps + 64 * 68;
    float* rowL = rowM + 64;
    float* rowS = rowL + 64;

    const int tid = threadIdx.x;
    const int qi = blockIdx.x, h = blockIdx.y, b = blockIdx.z;
    const int q0 = qi * 64;

    const int ldr = tid >> 2;
    const int ldc = (tid & 3) * 32;

    {
        const float qs = 0.08838834764831845f;
        const float* src = Qg + ((size_t)(b * S_LEN + q0 + ldr)) * DIM + h * HD + ldc;
        #pragma unroll
        for (int j = 0; j < 8; j++) {
            float4 v = *(const float4*)(src + j * 4);
            const int c = ldc + j * 4;
            Qt[(c + 0) * 68 + ldr] = v.x * qs;
            Qt[(c + 1) * 68 + ldr] = v.y * qs;
            Qt[(c + 2) * 68 + ldr] = v.z * qs;
            Qt[(c + 3) * 68 + ldr] = v.w * qs;
        }
    }
    if (tid < 64) { rowM[tid] = -1e30f; rowL[tid] = 0.0f; }

    u64 accO[4][4];
    #pragma unroll
    for (int i = 0; i < 4; i++)
        #pragma unroll
        for (int j = 0; j < 4; j++) accO[i][j] = 0ull;

    const int warp = tid >> 5, lane = tid & 31;
    const int wm = warp >> 1, wn = warp & 1;
    const int sr0 = wm * 16 + (lane >> 3) * 4;
    const int sc0 = wn * 32 + (lane & 7) * 4;
    const int tr2 = tid >> 4, tc2 = tid & 15;
    const int seg = tid & 3, srow = tid >> 2;

    for (int kt = 0; kt <= qi; kt++) {
        __syncthreads();
        {
            const size_t rb = ((size_t)(b * S_LEN + kt * 64 + ldr)) * DIM + h * HD + ldc;
            const float* ksrc = Kg + rb;
            const float* vsrc = Vg + rb;
            #pragma unroll
            for (int j = 0; j < 8; j++) {
                float4 kv = *(const float4*)(ksrc + j * 4);
                const int c = ldc + j * 4;
                Kt[(c + 0) * 68 + ldr] = kv.x;
                Kt[(c + 1) * 68 + ldr] = kv.y;
                Kt[(c + 2) * 68 + ldr] = kv.z;
                Kt[(c + 3) * 68 + ldr] = kv.w;
                *(float4*)(Vs + ldr * 132 + c) = *(const float4*)(vsrc + j * 4);
            }
        }
        __syncthreads();

        u64 acc2[4][4];
        #pragma unroll
        for (int i = 0; i < 4; i++)
            #pragma unroll
            for (int j = 0; j < 4; j++) acc2[i][j] = 0ull;

        #pragma unroll 4
        for (int d2 = 0; d2 < 64; d2++) {
            const float* qr0 = Qt + (2 * d2) * 68;
            const float* kr0 = Kt + (2 * d2) * 68;
            float4 qa = *(const float4*)(qr0 + sr0);
            float4 qb = *(const float4*)(qr0 + 68 + sr0);
            float4 ka = *(const float4*)(kr0 + sc0);
            float4 kb = *(const float4*)(kr0 + 68 + sc0);
            u64 qp[4] = { pk2(qa.x, qb.x), pk2(qa.y, qb.y), pk2(qa.z, qb.z), pk2(qa.w, qb.w) };
            u64 kp[4] = { pk2(ka.x, kb.x), pk2(ka.y, kb.y), pk2(ka.z, kb.z), pk2(ka.w, kb.w) };
            #pragma unroll
            for (int i = 0; i < 4; i++)
                #pragma unroll
                for (int j = 0; j < 4; j++) fma2(acc2[i][j], qp[i], kp[j]);
        }

        const bool diag = (kt == qi);
        #pragma unroll
        for (int i = 0; i < 4; i++) {
            float sv[4];
            #pragma unroll
            for (int j = 0; j < 4; j++) {
                float2 p = upk2(acc2[i][j]);
                float s = p.x + p.y;
                if (diag && (sc0 + j) > (sr0 + i)) s = -1e30f;
                sv[j] = s;
            }
            *(float4*)(Ps + (sr0 + i) * 68 + sc0) = make_float4(sv[0], sv[1], sv[2], sv[3]);
        }
        __syncthreads();

        {
            float* prow = Ps + srow * 68 + seg * 16;
            float xv[16];
            #pragma unroll
            for (int j = 0; j < 4; j++) {
                float4 v = *(const float4*)(prow + j * 4);
                xv[j*4+0] = v.x; xv[j*4+1] = v.y; xv[j*4+2] = v.z; xv[j*4+3] = v.w;
            }
            float mloc = -1e30f;
            #pragma unroll
            for (int j = 0; j < 16; j++) mloc = fmaxf(mloc, xv[j]);
            mloc = fmaxf(mloc, __shfl_xor_sync(0xffffffffu, mloc, 1));
            mloc = fmaxf(mloc, __shfl_xor_sync(0xffffffffu, mloc, 2));

            const float mold = rowM[srow];
            const float mnew = fmaxf(mold, mloc);
            const float fac  = __expf(mold - mnew);

            float ssum = 0.0f;
            #pragma unroll
            for (int j = 0; j < 16; j++) { xv[j] = __expf(xv[j] - mnew); ssum += xv[j]; }
            #pragma unroll
            for (int j = 0; j < 4; j++)
                *(float4*)(prow + j * 4) = make_float4(xv[j*4+0], xv[j*4+1], xv[j*4+2], xv[j*4+3]);

            ssum += __shfl_xor_sync(0xffffffffu, ssum, 1);
            ssum += __shfl_xor_sync(0xffffffffu, ssum, 2);
            if (seg == 0) {
                rowM[srow] = mnew;
                rowL[srow] = rowL[srow] * fac + ssum;
                rowS[srow] = fac;
            }
        }
        __syncthreads();

        #pragma unroll
        for (int i = 0; i < 4; i++) {
            const float f = rowS[tr2 * 4 + i];
            const u64 fd = pk2(f, f);
            #pragma unroll
            for (int j = 0; j < 4; j++) accO[i][j] = mul2(accO[i][j], fd);
        }
        #pragma unroll 4
        for (int k = 0; k < 64; k++) {
            float4 v0 = *(const float4*)(Vs + k * 132 + tc2 * 4);
            float4 v1 = *(const float4*)(Vs + k * 132 + 64 + tc2 * 4);
            u64 vb[4] = { pk2(v0.x, v0.y), pk2(v0.z, v0.w),
                          pk2(v1.x, v1.y), pk2(v1.z, v1.w) };
            #pragma unroll
            for (int i = 0; i < 4; i++) {
                const float p = Ps[(tr2 * 4 + i) * 68 + k];
                const u64 pd = pk2(p, p);
                #pragma unroll
                for (int j = 0; j < 4; j++) fma2(accO[i][j], pd, vb[j]);
            }
        }
    }

    #pragma unroll
    for (int i = 0; i < 4; i++) {
        const int r = tr2 * 4 + i;
        const float inv = 1.0f / rowL[r];
        const u64 iv = pk2(inv, inv);
        float2 a0 = upk2(mul2(accO[i][0], iv));
        float2 a1 = upk2(mul2(accO[i][1], iv));
        float2 a2 = upk2(mul2(accO[i][2], iv));
        float2 a3 = upk2(mul2(accO[i][3], iv));
        float* dst = Og + ((size_t)(b * S_LEN + q0 + r)) * DIM + h * HD;
        *(float4*)(dst + tc2 * 4)      = make_float4(a0.x, a0.y, a1.x, a1.y);
        *(float4*)(dst + 64 + tc2 * 4) = make_float4(a2.x, a2.y, a3.x, a3.y);
    }
}

#define ATT_SMEM_BYTES ((128*68*2 + 64*132 + 64*68 + 192) * 4)

extern "C" void kernel_launch(void* const* d_in, const int* in_sizes, int n_in,
                              void* d_out, int out_size)
{
    const float* x  = (const float*)d_in[0];
    const float* wq = (const float*)d_in[1];
    const float* wk = (const float*)d_in[2];
    const float* wv = (const float*)d_in[3];
    const float* wo = (const float*)d_in[4];
    const float* fc = (const float*)d_in[5];
    const float* fs = (const float*)d_in[6];
    float* out = (float*)d_out;

    float *q, *k, *v, *att;
    __nv_bfloat16 *xh, *xl, *wqh, *wql, *wkh, *wkl, *wvh, *wvl, *woh, *wol, *ah, *al;
    cudaGetSymbolAddress((void**)&q,   g_q);
    cudaGetSymbolAddress((void**)&k,   g_k);
    cudaGetSymbolAddress((void**)&v,   g_v);
    cudaGetSymbolAddress((void**)&att, g_att);
    cudaGetSymbolAddress((void**)&xh,  g_xh);   cudaGetSymbolAddress((void**)&xl,  g_xl);
    cudaGetSymbolAddress((void**)&wqh, g_wqh);  cudaGetSymbolAddress((void**)&wql, g_wql);
    cudaGetSymbolAddress((void**)&wkh, g_wkh);  cudaGetSymbolAddress((void**)&wkl, g_wkl);
    cudaGetSymbolAddress((void**)&wvh, g_wvh);  cudaGetSymbolAddress((void**)&wvl, g_wvl);
    cudaGetSymbolAddress((void**)&woh, g_woh);  cudaGetSymbolAddress((void**)&wol, g_wol);
    cudaGetSymbolAddress((void**)&ah,  g_ah);   cudaGetSymbolAddress((void**)&al,  g_al);

    cudaFuncSetAttribute(flash_attn, cudaFuncAttributeMaxDynamicSharedMemorySize, ATT_SMEM_BYTES);
    cudaFuncSetAttribute(gemm_hmma3, cudaFuncAttributeMaxDynamicSharedMemorySize, GEMM_SMEM);

    const int splitBlocks = (DIM * DIM / 4) / 256;
    split_bf16<<<splitBlocks, 256>>>(x,  xh,  xl);
    split_bf16<<<splitBlocks, 256>>>(wq, wqh, wql);
    split_bf16<<<splitBlocks, 256>>>(wk, wkh, wkl);
    split_bf16<<<splitBlocks, 256>>>(wv, wvh, wvl);
    split_bf16<<<splitBlocks, 256>>>(wo, woh, wol);

    dim3 gt(32, 32);
    gemm_hmma3<<<gt, 256, GEMM_SMEM>>>(xh, xl, wqh, wql, q);
    gemm_hmma3<<<gt, 256, GEMM_SMEM>>>(xh, xl, wkh, wkl, k);
    gemm_hmma3<<<gt, 256, GEMM_SMEM>>>(xh, xl, wvh, wvl, v);

    rope_kernel<<<(MTOT * NH * 64) / 256, 256>>>(q, k, fc, fs);

    dim3 ga(S_LEN / 64, NH, BATCH);
    flash_attn<<<ga, 256, ATT_SMEM_BYTES>>>(q, k, v, att);

    split_bf16<<<splitBlocks, 256>>>(att, ah, al);
    gemm_hmma3<<<gt, 256, GEMM_SMEM>>>(ah, al, woh, wol, out);
}

// round 11
// speedup vs baseline: 2.3524x; 1.4572x over previous
#include <cuda_runtime.h>
#include <cuda_bf16.h>
#include <cstdint>
#include <cstddef>

#define S_LEN 2048
#define DIM   4096
#define NH    32
#define HD    128
#define BATCH 2
#define MTOT  (BATCH*S_LEN)

typedef unsigned long long u64;
typedef unsigned int u32;
typedef unsigned short u16;

// ---------------- helpers ----------------
__device__ __forceinline__ u32 smem_u32(const void* p){
    u32 a; asm("{ .reg .u64 t; cvta.to.shared.u64 t, %1; cvt.u32.u64 %0, t; }" : "=r"(a) : "l"(p));
    return a;
}
__device__ __forceinline__ void mma16816(float* c, const u32* a, const u32* b){
    asm volatile("mma.sync.aligned.m16n8k16.row.col.f32.bf16.bf16.f32 "
        "{%0,%1,%2,%3}, {%4,%5,%6,%7}, {%8,%9}, {%0,%1,%2,%3};"
        : "+f"(c[0]), "+f"(c[1]), "+f"(c[2]), "+f"(c[3])
        : "r"(a[0]), "r"(a[1]), "r"(a[2]), "r"(a[3]), "r"(b[0]), "r"(b[1]));
}
__device__ __forceinline__ void ldsm4(u32* r, u32 addr){
    asm volatile("ldmatrix.sync.aligned.m8n8.x4.shared.b16 {%0,%1,%2,%3}, [%4];"
        : "=r"(r[0]), "=r"(r[1]), "=r"(r[2]), "=r"(r[3]) : "r"(addr));
}
__device__ __forceinline__ void ldsm4t(u32* r, u32 addr){
    asm volatile("ldmatrix.sync.aligned.m8n8.x4.trans.shared.b16 {%0,%1,%2,%3}, [%4];"
        : "=r"(r[0]), "=r"(r[1]), "=r"(r[2]), "=r"(r[3]) : "r"(addr));
}
__device__ __forceinline__ void cpa16(u32 dst, const void* src){
    asm volatile("cp.async.cg.shared.global [%0], [%1], 16;" :: "r"(dst), "l"(src) : "memory");
}
__device__ __forceinline__ u32 pkbf(float a, float b){   // low = a, high = b
    u16 ha = __bfloat16_as_ushort(__float2bfloat16_rn(a));
    u16 hb = __bfloat16_as_ushort(__float2bfloat16_rn(b));
    return (u32)ha | ((u32)hb << 16);
}

// ---------------- scratch ----------------
__device__ float g_q[(size_t)MTOT*DIM];
__device__ float g_k[(size_t)MTOT*DIM];
__device__ float g_v[(size_t)MTOT*DIM];
__device__ __nv_bfloat16 g_xh[(size_t)MTOT*DIM],  g_xl[(size_t)MTOT*DIM];
__device__ __nv_bfloat16 g_wqh[(size_t)DIM*DIM], g_wql[(size_t)DIM*DIM];
__device__ __nv_bfloat16 g_wkh[(size_t)DIM*DIM], g_wkl[(size_t)DIM*DIM];
__device__ __nv_bfloat16 g_wvh[(size_t)DIM*DIM], g_wvl[(size_t)DIM*DIM];
__device__ __nv_bfloat16 g_woh[(size_t)DIM*DIM], g_wol[(size_t)DIM*DIM];
__device__ __nv_bfloat16 g_ah[(size_t)MTOT*DIM], g_al[(size_t)MTOT*DIM];

// ============ fp32 -> (bf16 hi, bf16 lo) split ============
__global__ __launch_bounds__(256)
void split_bf16(const float* __restrict__ s,
                __nv_bfloat16* __restrict__ h, __nv_bfloat16* __restrict__ l)
{
    const size_t i = ((size_t)blockIdx.x * 256 + threadIdx.x) * 4;
    float4 v = *(const float4*)(s + i);
    float xs[4] = { v.x, v.y, v.z, v.w };
    u16 hs[4], ls[4];
    #pragma unroll
    for (int j = 0; j < 4; j++) {
        __nv_bfloat16 hb = __float2bfloat16_rn(xs[j]);
        float res = xs[j] - __bfloat162float(hb);
        hs[j] = __bfloat16_as_ushort(hb);
        ls[j] = __bfloat16_as_ushort(__float2bfloat16_rn(res));
    }
    uint2 H, L;
    H.x = (u32)hs[0] | ((u32)hs[1] << 16);  H.y = (u32)hs[2] | ((u32)hs[3] << 16);
    L.x = (u32)ls[0] | ((u32)ls[1] << 16);  L.y = (u32)ls[2] | ((u32)ls[3] << 16);
    *(uint2*)(h + i) = H;
    *(uint2*)(l + i) = L;
}

// ============ 3xBF16 HMMA GEMM (unchanged from R10, passing) ============
#define LDT    40
#define ARR_B  (128*LDT*2)
#define STAGE  (4*ARR_B)
#define GEMM_SMEM (2*STAGE)

__global__ __launch_bounds__(256, 2)
void gemm_hmma3(const __nv_bfloat16* __restrict__ Ah, const __nv_bfloat16* __restrict__ Al,
                const __nv_bfloat16* __restrict__ Bh, const __nv_bfloat16* __restrict__ Bl,
                float* __restrict__ C)
{
    extern __shared__ char dsm[];
    const u32 sbase = smem_u32(dsm);

    const int tid  = threadIdx.x;
    const int brow = blockIdx.y, bcol = blockIdx.x;
    const int warp = tid >> 5, lane = tid & 31;
    const int wm = warp >> 1, wn = warp & 1;

    float acc[2][8][4];
    #pragma unroll
    for (int i = 0; i < 2; i++)
        #pragma unroll
        for (int j = 0; j < 8; j++)
            #pragma unroll
            for (int q = 0; q < 4; q++) acc[i][j][q] = 0.0f;

    const int idx0 = tid, idx1 = tid + 256;
    const int row0 = idx0 >> 2, c80 = (idx0 & 3) * 8;
    const int row1 = idx1 >> 2, c81 = (idx1 & 3) * 8;

    #define PREFETCH(kt) do {                                                        \
        const u32 sb = sbase + ((kt) & 1) * STAGE;                                   \
        const size_t ga0 = (size_t)(brow*128 + row0)*DIM + (size_t)(kt)*32 + c80;    \
        const size_t gb0 = (size_t)(bcol*128 + row0)*DIM + (size_t)(kt)*32 + c80;    \
        const size_t ga1 = (size_t)(brow*128 + row1)*DIM + (size_t)(kt)*32 + c81;    \
        const size_t gb1 = (size_t)(bcol*128 + row1)*DIM + (size_t)(kt)*32 + c81;    \
        const u32 s0 = sb + (u32)(row0*80 + c80*2);                                  \
        const u32 s1 = sb + (u32)(row1*80 + c81*2);                                  \
        cpa16(s0,             Ah + ga0);  cpa16(s1,             Ah + ga1);           \
        cpa16(s0 + ARR_B,     Al + ga0);  cpa16(s1 + ARR_B,     Al + ga1);           \
        cpa16(s0 + 2*ARR_B,   Bh + gb0);  cpa16(s1 + 2*ARR_B,   Bh + gb1);           \
        cpa16(s0 + 3*ARR_B,   Bl + gb0);  cpa16(s1 + 3*ARR_B,   Bl + gb1);           \
        asm volatile("cp.async.commit_group;" ::: "memory");                         \
    } while (0)

    PREFETCH(0);

    const int a_r = (lane & 15);
    const int a_c = (lane >> 4) * 8;
    const int b_r = (lane & 7) + ((lane >> 4) * 8);
    const int b_c = ((lane >> 3) & 1) * 8;

    #pragma unroll 1
    for (int kt = 0; kt < 128; kt++) {
        if (kt + 1 < 128) {
            PREFETCH(kt + 1);
            asm volatile("cp.async.wait_group 1;" ::: "memory");
        } else {
            asm volatile("cp.async.wait_group 0;" ::: "memory");
        }
        __syncthreads();

        const u32 aB  = sbase + (kt & 1) * STAGE;
        const u32 alB = aB + ARR_B;
        const u32 bhB = aB + 2*ARR_B;
        const u32 blB = aB + 3*ARR_B;

        #pragma unroll
        for (int ks = 0; ks < 2; ks++) {
            const int k0 = ks * 16;
            u32 ahf[2][4], alf[2][4];
            #pragma unroll
            for (int mf = 0; mf < 2; mf++) {
                const u32 off = (u32)((wm*32 + mf*16 + a_r) * 80 + (k0 + a_c) * 2);
                ldsm4(ahf[mf], aB  + off);
                ldsm4(alf[mf], alB + off);
            }
            #pragma unroll
            for (int nf2 = 0; nf2 < 4; nf2++) {
                const u32 offb = (u32)((wn*64 + nf2*16 + b_r) * 80 + (k0 + b_c) * 2);
                u32 bhf[4], blf[4];
                ldsm4(bhf, bhB + offb);
                ldsm4(blf, blB + offb);
                #pragma unroll
                for (int mf = 0; mf < 2; mf++) {
                    #pragma unroll
                    for (int h = 0; h < 2; h++) {
                        float* c = acc[mf][nf2*2 + h];
                        mma16816(c, ahf[mf], bhf + 2*h);
                        mma16816(c, alf[mf], bhf + 2*h);
                        mma16816(c, ahf[mf], blf + 2*h);
                    }
                }
            }
        }
        __syncthreads();
    }

    #pragma unroll
    for (int mf = 0; mf < 2; mf++) {
        #pragma unroll
        for (int nf = 0; nf < 8; nf++) {
            const int r0 = brow*128 + wm*32 + mf*16 + (lane >> 2);
            const int c0 = bcol*128 + wn*64 + nf*8 + (lane & 3)*2;
            float* p = C + (size_t)r0 * DIM + c0;
            *(float2*)p             = make_float2(acc[mf][nf][0], acc[mf][nf][1]);
            *(float2*)(p + 8*DIM)   = make_float2(acc[mf][nf][2], acc[mf][nf][3]);
        }
    }
    #undef PREFETCH
}

// ============ RoPE in-place on Q and K ============
__global__ void rope_kernel(float* __restrict__ q, float* __restrict__ k,
                            const float* __restrict__ cosT, const float* __restrict__ sinT)
{
    const int idx = blockIdx.x * blockDim.x + threadIdx.x;
    const int d2 = idx & 63;
    const int t  = idx >> 6;
    const int hh = t & (NH - 1);
    const int bs = t >> 5;
    const int s  = bs & (S_LEN - 1);

    const float c  = cosT[(s << 6) + d2];
    const float sn = sinT[(s << 6) + d2];
    const size_t base = ((size_t)bs << 12) + ((size_t)hh << 7) + ((size_t)d2 << 1);

    float2 qv = *(float2*)(q + base);
    float2 kv = *(float2*)(k + base);
    float2 qo, ko;
    qo.x = qv.x * c - qv.y * sn;  qo.y = qv.x * sn + qv.y * c;
    ko.x = kv.x * c - kv.y * sn;  ko.y = kv.x * sn + kv.y * c;
    *(float2*)(q + base) = qo;
    *(float2*)(k + base) = ko;
}

// ============ HMMA flash attention (causal) ============
// CTA: 128 q-rows x (head, batch). 8 warps x 16-row warp tiles. kv-tile = 128.
// smem: Qh Ql Kh Kl Vh Vl, each [128][136] bf16 (= 34816 B). Total 208896 B.
#define LDV 136
#define FARR (128*LDV*2)
#define FLASH_SMEM (6*FARR)

__global__ __launch_bounds__(256, 1)
void flash_hmma(const float* __restrict__ Qg, const float* __restrict__ Kg,
                const float* __restrict__ Vg,
                __nv_bfloat16* __restrict__ Oh, __nv_bfloat16* __restrict__ Ol)
{
    extern __shared__ char fsm[];
    const u32 QH = smem_u32(fsm);
    const u32 QL = QH + FARR;
    const u32 KH = QH + 2*FARR;
    const u32 KL = QH + 3*FARR;
    const u32 VH = QH + 4*FARR;
    const u32 VL = QH + 5*FARR;

    const int tid = threadIdx.x;
    const int w = tid >> 5, lane = tid & 31;
    const int qi = (int)gridDim.x - 1 - (int)blockIdx.x;   // heavy CTAs first
    const int h = blockIdx.y, b = blockIdx.z;
    const int q0 = qi * 128;
    const int R = w * 16;

    // per-lane ldmatrix address components
    const int qrow_l = (lane & 7) + ((lane >> 3) & 1) * 8;   // A-pattern row
    const int qcol_l = (lane >> 4) * 8;                       // A-pattern col
    const int krow_l = (lane & 7) + (lane >> 4) * 8;          // K B-pattern row
    const int kcol_l = ((lane >> 3) & 1) * 8;                 // K B-pattern col
    const int vrow_l = (lane & 7) + ((lane >> 3) & 1) * 8;    // V trans row
    const int vcol_l = (lane >> 4) * 8;                       // V trans col

    // ---- load + split Q (scaled) ----
    {
        const float qs = 0.08838834764831845f;   // 1/sqrt(128)
        const int row = tid >> 1;
        const int c0 = (tid & 1) * 64;
        const float* src = Qg + ((size_t)(b * S_LEN + q0 + row)) * DIM + h * HD + c0;
        #pragma unroll
        for (int j = 0; j < 16; j++) {
            float4 v = *(const float4*)(src + j * 4);
            float xs[4] = { v.x * qs, v.y * qs, v.z * qs, v.w * qs };
            u16 hs[4], ls[4];
            #pragma unroll
            for (int e = 0; e < 4; e++) {
                __nv_bfloat16 hb = __float2bfloat16_rn(xs[e]);
                hs[e] = __bfloat16_as_ushort(hb);
                ls[e] = __bfloat16_as_ushort(__float2bfloat16_rn(xs[e] - __bfloat162float(hb)));
            }
            uint2 H = { (u32)hs[0] | ((u32)hs[1] << 16), (u32)hs[2] | ((u32)hs[3] << 16) };
            uint2 L = { (u32)ls[0] | ((u32)ls[1] << 16), (u32)ls[2] | ((u32)ls[3] << 16) };
            const u32 off = (u32)(row * LDV + c0 + j * 4) * 2;
            *(uint2*)(u64)(0) ; // placeholder removed below
            // store via smem pointer arithmetic
            *((uint2*)(fsm + (off)))            = H;   // QH region (fsm base == QH)
            *((uint2*)(fsm + FARR + off))       = L;
        }
    }

    float S[16][4], O[16][4];
    #pragma unroll
    for (int n = 0; n < 16; n++)
        #pragma unroll
        for (int j = 0; j < 4; j++) O[n][j] = 0.0f;
    float m0 = -1e30f, m1 = -1e30f, l0 = 0.0f, l1 = 0.0f;

    #pragma unroll 1
    for (int kt = 0; kt <= qi; kt++) {
        __syncthreads();
        // ---- load + split K, V ----
        {
            const int row = tid >> 1;
            const int c0 = (tid & 1) * 64;
            const size_t rb = ((size_t)(b * S_LEN + kt * 128 + row)) * DIM + h * HD + c0;
            const float* ks = Kg + rb;
            const float* vs = Vg + rb;
            #pragma unroll
            for (int j = 0; j < 16; j++) {
                float4 kv = *(const float4*)(ks + j * 4);
                float4 vv = *(const float4*)(vs + j * 4);
                float xk[4] = { kv.x, kv.y, kv.z, kv.w };
                float xv[4] = { vv.x, vv.y, vv.z, vv.w };
                u16 kh_[4], kl_[4], vh_[4], vl_[4];
                #pragma unroll
                for (int e = 0; e < 4; e++) {
                    __nv_bfloat16 hb = __float2bfloat16_rn(xk[e]);
                    kh_[e] = __bfloat16_as_ushort(hb);
                    kl_[e] = __bfloat16_as_ushort(__float2bfloat16_rn(xk[e] - __bfloat162float(hb)));
                    __nv_bfloat16 vb = __float2bfloat16_rn(xv[e]);
                    vh_[e] = __bfloat16_as_ushort(vb);
                    vl_[e] = __bfloat16_as_ushort(__float2bfloat16_rn(xv[e] - __bfloat162float(vb)));
                }
                const u32 off = (u32)(row * LDV + c0 + j * 4) * 2;
                uint2 KHv = { (u32)kh_[0] | ((u32)kh_[1] << 16), (u32)kh_[2] | ((u32)kh_[3] << 16) };
                uint2 KLv = { (u32)kl_[0] | ((u32)kl_[1] << 16), (u32)kl_[2] | ((u32)kl_[3] << 16) };
                uint2 VHv = { (u32)vh_[0] | ((u32)vh_[1] << 16), (u32)vh_[2] | ((u32)vh_[3] << 16) };
                uint2 VLv = { (u32)vl_[0] | ((u32)vl_[1] << 16), (u32)vl_[2] | ((u32)vl_[3] << 16) };
                *((uint2*)(fsm + 2*FARR + off)) = KHv;
                *((uint2*)(fsm + 3*FARR + off)) = KLv;
                *((uint2*)(fsm + 4*FARR + off)) = VHv;
                *((uint2*)(fsm + 5*FARR + off)) = VLv;
            }
        }
        __syncthreads();

        // ---- S = Q K^T (3-term) ----
        #pragma unroll
        for (int n = 0; n < 16; n++)
            #pragma unroll
            for (int j = 0; j < 4; j++) S[n][j] = 0.0f;

        #pragma unroll
        for (int ks = 0; ks < 8; ks++) {
            u32 qh[4], ql[4];
            const u32 qoff = (u32)((R + qrow_l) * LDV + ks * 16 + qcol_l) * 2;
            ldsm4(qh, QH + qoff);
            ldsm4(ql, QL + qoff);
            #pragma unroll
            for (int n2 = 0; n2 < 8; n2++) {
                u32 kh[4], kl[4];
                const u32 koff = (u32)((n2 * 16 + krow_l) * LDV + ks * 16 + kcol_l) * 2;
                ldsm4(kh, KH + koff);
                ldsm4(kl, KL + koff);
                mma16816(S[2*n2],     qh, kh);     mma16816(S[2*n2],     ql, kh);     mma16816(S[2*n2],     qh, kl);
                mma16816(S[2*n2 + 1], qh, kh + 2); mma16816(S[2*n2 + 1], ql, kh + 2); mma16816(S[2*n2 + 1], qh, kl + 2);
            }
        }

        // ---- causal mask on diagonal tile ----
        if (kt == qi) {
            const int r_lo = R + (lane >> 2);
            #pragma unroll
            for (int n = 0; n < 16; n++) {
                const int c = n * 8 + (lane & 3) * 2;
                if (c     > r_lo)     S[n][0] = -1e30f;
                if (c + 1 > r_lo)     S[n][1] = -1e30f;
                if (c     > r_lo + 8) S[n][2] = -1e30f;
                if (c + 1 > r_lo + 8) S[n][3] = -1e30f;
            }
        }

        // ---- online softmax ----
        {
            float mx0 = -1e30f, mx1 = -1e30f;
            #pragma unroll
            for (int n = 0; n < 16; n++) {
                mx0 = fmaxf(mx0, fmaxf(S[n][0], S[n][1]));
                mx1 = fmaxf(mx1, fmaxf(S[n][2], S[n][3]));
            }
            mx0 = fmaxf(mx0, __shfl_xor_sync(0xffffffffu, mx0, 1));
            mx0 = fmaxf(mx0, __shfl_xor_sync(0xffffffffu, mx0, 2));
            mx1 = fmaxf(mx1, __shfl_xor_sync(0xffffffffu, mx1, 1));
            mx1 = fmaxf(mx1, __shfl_xor_sync(0xffffffffu, mx1, 2));

            const float m0n = fmaxf(m0, mx0);
            const float m1n = fmaxf(m1, mx1);
            const float f0 = __expf(m0 - m0n);
            const float f1 = __expf(m1 - m1n);

            float s0 = 0.0f, s1 = 0.0f;
            #pragma unroll
            for (int n = 0; n < 16; n++) {
                S[n][0] = __expf(S[n][0] - m0n); s0 += S[n][0];
                S[n][1] = __expf(S[n][1] - m0n); s0 += S[n][1];
                S[n][2] = __expf(S[n][2] - m1n); s1 += S[n][2];
                S[n][3] = __expf(S[n][3] - m1n); s1 += S[n][3];
            }
            s0 += __shfl_xor_sync(0xffffffffu, s0, 1);
            s0 += __shfl_xor_sync(0xffffffffu, s0, 2);
            s1 += __shfl_xor_sync(0xffffffffu, s1, 1);
            s1 += __shfl_xor_sync(0xffffffffu, s1, 2);

            l0 = l0 * f0 + s0;  l1 = l1 * f1 + s1;
            m0 = m0n;           m1 = m1n;

            #pragma unroll
            for (int n = 0; n < 16; n++) {
                O[n][0] *= f0;  O[n][1] *= f0;
                O[n][2] *= f1;  O[n][3] *= f1;
            }
        }

        // ---- O += P V (3-term; P frags built from S registers) ----
        #pragma unroll
        for (int ks = 0; ks < 8; ks++) {
            u32 ph[4], pl[4];
            #pragma unroll
            for (int t = 0; t < 4; t++) {
                const int n = 2*ks + (t >> 1);
                const int j0 = (t & 1) * 2;
                const float p0 = S[n][j0], p1 = S[n][j0 + 1];
                const __nv_bfloat16 h0 = __float2bfloat16_rn(p0);
                const __nv_bfloat16 h1 = __float2bfloat16_rn(p1);
                ph[t] = (u32)__bfloat16_as_ushort(h0) | ((u32)__bfloat16_as_ushort(h1) << 16);
                pl[t] = pkbf(p0 - __bfloat162float(h0), p1 - __bfloat162float(h1));
            }
            #pragma unroll
            for (int n2 = 0; n2 < 8; n2++) {
                u32 vh[4], vl[4];
                const u32 voff = (u32)((ks * 16 + vrow_l) * LDV + n2 * 16 + vcol_l) * 2;
                ldsm4t(vh, VH + voff);
                ldsm4t(vl, VL + voff);
                mma16816(O[2*n2],     ph, vh);     mma16816(O[2*n2],     pl, vh);     mma16816(O[2*n2],     ph, vl);
                mma16816(O[2*n2 + 1], ph, vh + 2); mma16816(O[2*n2 + 1], pl, vh + 2); mma16816(O[2*n2 + 1], ph, vl + 2);
            }
        }
    }

    // ---- epilogue: normalize, split to bf16 hi/lo, store ----
    {
        const float inv0 = 1.0f / l0;
        const float inv1 = 1.0f / l1;
        const size_t row0 = (size_t)(b * S_LEN + q0 + R + (lane >> 2));
        const size_t row1 = row0 + 8;
        const int colb = h * HD + (lane & 3) * 2;
        #pragma unroll
        for (int n = 0; n < 16; n++) {
            const int col = colb + n * 8;
            float o0 = O[n][0] * inv0, o1 = O[n][1] * inv0;
            float o2 = O[n][2] * inv1, o3 = O[n][3] * inv1;
            const __nv_bfloat16 h0 = __float2bfloat16_rn(o0), h1 = __float2bfloat16_rn(o1);
            const __nv_bfloat16 h2 = __float2bfloat16_rn(o2), h3 = __float2bfloat16_rn(o3);
            *(u32*)(Oh + row0 * DIM + col) = (u32)__bfloat16_as_ushort(h0) | ((u32)__bfloat16_as_ushort(h1) << 16);
            *(u32*)(Oh + row1 * DIM + col) = (u32)__bfloat16_as_ushort(h2) | ((u32)__bfloat16_as_ushort(h3) << 16);
            *(u32*)(Ol + row0 * DIM + col) = pkbf(o0 - __bfloat162float(h0), o1 - __bfloat162float(h1));
            *(u32*)(Ol + row1 * DIM + col) = pkbf(o2 - __bfloat162float(h2), o3 - __bfloat162float(h3));
        }
    }
}

extern "C" void kernel_launch(void* const* d_in, const int* in_sizes, int n_in,
                              void* d_out, int out_size)
{
    const float* x  = (const float*)d_in[0];
    const float* wq = (const float*)d_in[1];
    const float* wk = (const float*)d_in[2];
    const float* wv = (const float*)d_in[3];
    const float* wo = (const float*)d_in[4];
    const float* fc = (const float*)d_in[5];
    const float* fs = (const float*)d_in[6];
    float* out = (float*)d_out;

    float *q, *k, *v;
    __nv_bfloat16 *xh, *xl, *wqh, *wql, *wkh, *wkl, *wvh, *wvl, *woh, *wol, *ah, *al;
    cudaGetSymbolAddress((void**)&q,   g_q);
    cudaGetSymbolAddress((void**)&k,   g_k);
    cudaGetSymbolAddress((void**)&v,   g_v);
    cudaGetSymbolAddress((void**)&xh,  g_xh);   cudaGetSymbolAddress((void**)&xl,  g_xl);
    cudaGetSymbolAddress((void**)&wqh, g_wqh);  cudaGetSymbolAddress((void**)&wql, g_wql);
    cudaGetSymbolAddress((void**)&wkh, g_wkh);  cudaGetSymbolAddress((void**)&wkl, g_wkl);
    cudaGetSymbolAddress((void**)&wvh, g_wvh);  cudaGetSymbolAddress((void**)&wvl, g_wvl);
    cudaGetSymbolAddress((void**)&woh, g_woh);  cudaGetSymbolAddress((void**)&wol, g_wol);
    cudaGetSymbolAddress((void**)&ah,  g_ah);   cudaGetSymbolAddress((void**)&al,  g_al);

    cudaFuncSetAttribute(gemm_hmma3, cudaFuncAttributeMaxDynamicSharedMemorySize, GEMM_SMEM);
    cudaFuncSetAttribute(flash_hmma, cudaFuncAttributeMaxDynamicSharedMemorySize, FLASH_SMEM);

    const int splitBlocks = (DIM * DIM / 4) / 256;
    split_bf16<<<splitBlocks, 256>>>(x,  xh,  xl);
    split_bf16<<<splitBlocks, 256>>>(wq, wqh, wql);
    split_bf16<<<splitBlocks, 256>>>(wk, wkh, wkl);
    split_bf16<<<splitBlocks, 256>>>(wv, wvh, wvl);
    split_bf16<<<splitBlocks, 256>>>(wo, woh, wol);

    dim3 gt(32, 32);
    gemm_hmma3<<<gt, 256, GEMM_SMEM>>>(xh, xl, wqh, wql, q);
    gemm_hmma3<<<gt, 256, GEMM_SMEM>>>(xh, xl, wkh, wkl, k);
    gemm_hmma3<<<gt, 256, GEMM_SMEM>>>(xh, xl, wvh, wvl, v);

    rope_kernel<<<(MTOT * NH * 64) / 256, 256>>>(q, k, fc, fs);

    dim3 ga(S_LEN / 128, NH, BATCH);
    flash_hmma<<<ga, 256, FLASH_SMEM>>>(q, k, v, ah, al);

    gemm_hmma3<<<gt, 256, GEMM_SMEM>>>(ah, al, woh, wol, out);
}

// round 14
// speedup vs baseline: 2.4919x; 1.0593x over previous
#include <cuda_runtime.h>
#include <cuda_bf16.h>
#include <cstdint>
#include <cstddef>

#define S_LEN 2048
#define DIM   4096
#define NH    32
#define HD    128
#define BATCH 2
#define MTOT  (BATCH*S_LEN)

typedef unsigned long long u64;
typedef unsigned int u32;
typedef unsigned short u16;

// ---------------- helpers ----------------
__device__ __forceinline__ u32 smem_u32(const void* p){
    u32 a; asm("{ .reg .u64 t; cvta.to.shared.u64 t, %1; cvt.u32.u64 %0, t; }" : "=r"(a) : "l"(p));
    return a;
}
__device__ __forceinline__ void mma16816(float* c, const u32* a, const u32* b){
    asm volatile("mma.sync.aligned.m16n8k16.row.col.f32.bf16.bf16.f32 "
        "{%0,%1,%2,%3}, {%4,%5,%6,%7}, {%8,%9}, {%0,%1,%2,%3};"
        : "+f"(c[0]), "+f"(c[1]), "+f"(c[2]), "+f"(c[3])
        : "r"(a[0]), "r"(a[1]), "r"(a[2]), "r"(a[3]), "r"(b[0]), "r"(b[1]));
}
__device__ __forceinline__ void ldsm4(u32* r, u32 addr){
    asm volatile("ldmatrix.sync.aligned.m8n8.x4.shared.b16 {%0,%1,%2,%3}, [%4];"
        : "=r"(r[0]), "=r"(r[1]), "=r"(r[2]), "=r"(r[3]) : "r"(addr));
}
__device__ __forceinline__ void ldsm4t(u32* r, u32 addr){
    asm volatile("ldmatrix.sync.aligned.m8n8.x4.trans.shared.b16 {%0,%1,%2,%3}, [%4];"
        : "=r"(r[0]), "=r"(r[1]), "=r"(r[2]), "=r"(r[3]) : "r"(addr));
}
__device__ __forceinline__ void cpa16(u32 dst, const void* src){
    asm volatile("cp.async.cg.shared.global [%0], [%1], 16;" :: "r"(dst), "l"(src) : "memory");
}
__device__ __forceinline__ u32 pkbf(float a, float b){
    u16 ha = __bfloat16_as_ushort(__float2bfloat16_rn(a));
    u16 hb = __bfloat16_as_ushort(__float2bfloat16_rn(b));
    return (u32)ha | ((u32)hb << 16);
}
// split pair (a0,a1) -> H/L packed words at idx (adjacent cols)
__device__ __forceinline__ void store_split(__nv_bfloat16* H, __nv_bfloat16* L,
                                            size_t idx, float a0, float a1){
    const __nv_bfloat16 h0 = __float2bfloat16_rn(a0);
    const __nv_bfloat16 h1 = __float2bfloat16_rn(a1);
    *(u32*)(H + idx) = (u32)__bfloat16_as_ushort(h0) | ((u32)__bfloat16_as_ushort(h1) << 16);
    *(u32*)(L + idx) = pkbf(a0 - __bfloat162float(h0), a1 - __bfloat162float(h1));
}

// ---------------- scratch (all bf16 hi/lo pairs) ----------------
__device__ __nv_bfloat16 g_xh[(size_t)MTOT*DIM],  g_xl[(size_t)MTOT*DIM];
__device__ __nv_bfloat16 g_wqh[(size_t)DIM*DIM], g_wql[(size_t)DIM*DIM];
__device__ __nv_bfloat16 g_wkh[(size_t)DIM*DIM], g_wkl[(size_t)DIM*DIM];
__device__ __nv_bfloat16 g_wvh[(size_t)DIM*DIM], g_wvl[(size_t)DIM*DIM];
__device__ __nv_bfloat16 g_woh[(size_t)DIM*DIM], g_wol[(size_t)DIM*DIM];
__device__ __nv_bfloat16 g_qh[(size_t)MTOT*DIM], g_ql[(size_t)MTOT*DIM];
__device__ __nv_bfloat16 g_kh[(size_t)MTOT*DIM], g_kl[(size_t)MTOT*DIM];
__device__ __nv_bfloat16 g_vh[(size_t)MTOT*DIM], g_vl[(size_t)MTOT*DIM];
__device__ __nv_bfloat16 g_ah[(size_t)MTOT*DIM], g_al[(size_t)MTOT*DIM];

// ============ fp32 -> (bf16 hi, bf16 lo) split ============
__global__ __launch_bounds__(256)
void split_bf16(const float* __restrict__ s,
                __nv_bfloat16* __restrict__ h, __nv_bfloat16* __restrict__ l)
{
    const size_t i = ((size_t)blockIdx.x * 256 + threadIdx.x) * 4;
    float4 v = *(const float4*)(s + i);
    float xs[4] = { v.x, v.y, v.z, v.w };
    u16 hs[4], ls[4];
    #pragma unroll
    for (int j = 0; j < 4; j++) {
        __nv_bfloat16 hb = __float2bfloat16_rn(xs[j]);
        hs[j] = __bfloat16_as_ushort(hb);
        ls[j] = __bfloat16_as_ushort(__float2bfloat16_rn(xs[j] - __bfloat162float(hb)));
    }
    uint2 H, L;
    H.x = (u32)hs[0] | ((u32)hs[1] << 16);  H.y = (u32)hs[2] | ((u32)hs[3] << 16);
    L.x = (u32)ls[0] | ((u32)ls[1] << 16);  L.y = (u32)ls[2] | ((u32)ls[3] << 16);
    *(uint2*)(h + i) = H;
    *(uint2*)(l + i) = L;
}

// ============ GEMM core macros (shared by both GEMM kernels) ============
#define LDT    40
#define ARR_B  (128*LDT*2)
#define STAGE  (4*ARR_B)
#define GEMM_SMEM (2*STAGE)

#define GEMM_PREFETCH(kt, Ahp, Alp, Bhp, Blp) do {                               \
    const u32 sb = sbase + ((kt) & 1) * STAGE;                                   \
    const size_t ga0 = (size_t)(brow*128 + row0)*DIM + (size_t)(kt)*32 + c80;    \
    const size_t gb0 = (size_t)(bc*128   + row0)*DIM + (size_t)(kt)*32 + c80;    \
    const size_t ga1 = (size_t)(brow*128 + row1)*DIM + (size_t)(kt)*32 + c81;    \
    const size_t gb1 = (size_t)(bc*128   + row1)*DIM + (size_t)(kt)*32 + c81;    \
    const u32 s0 = sb + (u32)(row0*80 + c80*2);                                  \
    const u32 s1 = sb + (u32)(row1*80 + c81*2);                                  \
    cpa16(s0,             (Ahp) + ga0);  cpa16(s1,             (Ahp) + ga1);     \
    cpa16(s0 + ARR_B,     (Alp) + ga0);  cpa16(s1 + ARR_B,     (Alp) + ga1);     \
    cpa16(s0 + 2*ARR_B,   (Bhp) + gb0);  cpa16(s1 + 2*ARR_B,   (Bhp) + gb1);     \
    cpa16(s0 + 3*ARR_B,   (Blp) + gb0);  cpa16(s1 + 3*ARR_B,   (Blp) + gb1);     \
    asm volatile("cp.async.commit_group;" ::: "memory");                         \
} while (0)

#define GEMM_MAINLOOP(Ahp, Alp, Bhp, Blp)                                        \
    GEMM_PREFETCH(0, Ahp, Alp, Bhp, Blp);                                        \
    const int a_r = (lane & 15);                                                 \
    const int a_c = (lane >> 4) * 8;                                             \
    const int b_r = (lane & 7) + ((lane >> 4) * 8);                              \
    const int b_c = ((lane >> 3) & 1) * 8;                                       \
    _Pragma("unroll 1")                                                          \
    for (int kt = 0; kt < 128; kt++) {                                           \
        if (kt + 1 < 128) {                                                      \
            GEMM_PREFETCH(kt + 1, Ahp, Alp, Bhp, Blp);                           \
            asm volatile("cp.async.wait_group 1;" ::: "memory");                 \
        } else {                                                                 \
            asm volatile("cp.async.wait_group 0;" ::: "memory");                 \
        }                                                                        \
        __syncthreads();                                                         \
        const u32 aB  = sbase + (kt & 1) * STAGE;                                \
        const u32 alB = aB + ARR_B;                                              \
        const u32 bhB = aB + 2*ARR_B;                                            \
        const u32 blB = aB + 3*ARR_B;                                            \
        _Pragma("unroll")                                                        \
        for (int ks = 0; ks < 2; ks++) {                                         \
            const int k0 = ks * 16;                                              \
            u32 ahf[2][4], alf[2][4];                                            \
            _Pragma("unroll")                                                    \
            for (int mf = 0; mf < 2; mf++) {                                     \
                const u32 off = (u32)((wm*32 + mf*16 + a_r) * 80 + (k0 + a_c) * 2); \
                ldsm4(ahf[mf], aB  + off);                                       \
                ldsm4(alf[mf], alB + off);                                       \
            }                                                                    \
            _Pragma("unroll")                                                    \
            for (int nf2 = 0; nf2 < 4; nf2++) {                                  \
                const u32 offb = (u32)((wn*64 + nf2*16 + b_r) * 80 + (k0 + b_c) * 2); \
                u32 bhf[4], blf[4];                                              \
                ldsm4(bhf, bhB + offb);                                          \
                ldsm4(blf, blB + offb);                                          \
                _Pragma("unroll")                                                \
                for (int mf = 0; mf < 2; mf++) {                                 \
                    _Pragma("unroll")                                            \
                    for (int hh = 0; hh < 2; hh++) {                             \
                        float* c = acc[mf][nf2*2 + hh];                          \
                        mma16816(c, ahf[mf], bhf + 2*hh);                        \
                        mma16816(c, alf[mf], bhf + 2*hh);                        \
                        mma16816(c, ahf[mf], blf + 2*hh);                        \
                    }                                                            \
                }                                                                \
            }                                                                    \
        }                                                                        \
        __syncthreads();                                                         \
    }

// ============ Fused QKV GEMM + RoPE + split epilogue ============
// grid (96, 32): bcol/32 selects Q(0)/K(1)/V(2); writes bf16 hi/lo outputs.
__global__ __launch_bounds__(256, 2)
void gemm_qkv(const __nv_bfloat16* __restrict__ Ah, const __nv_bfloat16* __restrict__ Al,
              const __nv_bfloat16* __restrict__ Wqh, const __nv_bfloat16* __restrict__ Wql,
              const __nv_bfloat16* __restrict__ Wkh, const __nv_bfloat16* __restrict__ Wkl,
              const __nv_bfloat16* __restrict__ Wvh, const __nv_bfloat16* __restrict__ Wvl,
              __nv_bfloat16* __restrict__ Qh, __nv_bfloat16* __restrict__ Ql,
              __nv_bfloat16* __restrict__ Kh, __nv_bfloat16* __restrict__ Kl,
              __nv_bfloat16* __restrict__ Vh, __nv_bfloat16* __restrict__ Vl,
              const float* __restrict__ cosT, const float* __restrict__ sinT)
{
    extern __shared__ char dsm[];
    const u32 sbase = smem_u32(dsm);

    const int tid  = threadIdx.x;
    const int brow = blockIdx.y;
    const int which = blockIdx.x >> 5;          // 0=Q 1=K 2=V
    const int bc    = blockIdx.x & 31;
    const int warp = tid >> 5, lane = tid & 31;
    const int wm = warp >> 1, wn = warp & 1;

    const __nv_bfloat16* Bh = (which == 0) ? Wqh : (which == 1) ? Wkh : Wvh;
    const __nv_bfloat16* Bl = (which == 0) ? Wql : (which == 1) ? Wkl : Wvl;

    float acc[2][8][4];
    #pragma unroll
    for (int i = 0; i < 2; i++)
        #pragma unroll
        for (int j = 0; j < 8; j++)
            #pragma unroll
            for (int q = 0; q < 4; q++) acc[i][j][q] = 0.0f;

    const int idx0 = tid, idx1 = tid + 256;
    const int row0 = idx0 >> 2, c80 = (idx0 & 3) * 8;
    const int row1 = idx1 >> 2, c81 = (idx1 & 3) * 8;

    GEMM_MAINLOOP(Ah, Al, Bh, Bl)

    // epilogue: optional RoPE (+Q scaling), split to bf16 hi/lo
    __nv_bfloat16* OH = (which == 0) ? Qh : (which == 1) ? Kh : Vh;
    __nv_bfloat16* OL = (which == 0) ? Ql : (which == 1) ? Kl : Vl;
    const float qs = (which == 0) ? 0.08838834764831845f : 1.0f;

    #pragma unroll
    for (int mf = 0; mf < 2; mf++) {
        #pragma unroll
        for (int nf = 0; nf < 8; nf++) {
            const int r0 = brow*128 + wm*32 + mf*16 + (lane >> 2);
            const int c0 = bc*128 + wn*64 + nf*8 + (lane & 3)*2;
            float a0 = acc[mf][nf][0], a1 = acc[mf][nf][1];   // row r0,   cols c0, c0+1
            float a2 = acc[mf][nf][2], a3 = acc[mf][nf][3];   // row r0+8, cols c0, c0+1
            if (which < 2) {
                const int d2 = (c0 & (HD - 1)) >> 1;
                const int s0 = r0 & (S_LEN - 1);
                const int s1 = (r0 + 8) & (S_LEN - 1);
                const float cA = cosT[(s0 << 6) + d2], sA = sinT[(s0 << 6) + d2];
                const float cB = cosT[(s1 << 6) + d2], sB = sinT[(s1 << 6) + d2];
                float o0 = (a0 * cA - a1 * sA) * qs;
                float o1 = (a0 * sA + a1 * cA) * qs;
                float o2 = (a2 * cB - a3 * sB) * qs;
                float o3 = (a2 * sB + a3 * cB) * qs;
                a0 = o0; a1 = o1; a2 = o2; a3 = o3;
            }
            store_split(OH, OL, (size_t)r0 * DIM + c0, a0, a1);
            store_split(OH, OL, (size_t)(r0 + 8) * DIM + c0, a2, a3);
        }
    }
}

// ============ Output-projection GEMM (fp32 out) ============
__global__ __launch_bounds__(256, 2)
void gemm_out(const __nv_bfloat16* __restrict__ Ah, const __nv_bfloat16* __restrict__ Al,
              const __nv_bfloat16* __restrict__ Bh, const __nv_bfloat16* __restrict__ Bl,
              float* __restrict__ C)
{
    extern __shared__ char dsm[];
    const u32 sbase = smem_u32(dsm);

    const int tid  = threadIdx.x;
    const int brow = blockIdx.y;
    const int bc   = blockIdx.x;
    const int warp = tid >> 5, lane = tid & 31;
    const int wm = warp >> 1, wn = warp & 1;

    float acc[2][8][4];
    #pragma unroll
    for (int i = 0; i < 2; i++)
        #pragma unroll
        for (int j = 0; j < 8; j++)
            #pragma unroll
            for (int q = 0; q < 4; q++) acc[i][j][q] = 0.0f;

    const int idx0 = tid, idx1 = tid + 256;
    const int row0 = idx0 >> 2, c80 = (idx0 & 3) * 8;
    const int row1 = idx1 >> 2, c81 = (idx1 & 3) * 8;

    GEMM_MAINLOOP(Ah, Al, Bh, Bl)

    #pragma unroll
    for (int mf = 0; mf < 2; mf++) {
        #pragma unroll
        for (int nf = 0; nf < 8; nf++) {
            const int r0 = brow*128 + wm*32 + mf*16 + (lane >> 2);
            const int c0 = bc*128 + wn*64 + nf*8 + (lane & 3)*2;
            float* p = C + (size_t)r0 * DIM + c0;
            *(float2*)p           = make_float2(acc[mf][nf][0], acc[mf][nf][1]);
            *(float2*)(p + 8*DIM) = make_float2(acc[mf][nf][2], acc[mf][nf][3]);
        }
    }
}

// ============ HMMA flash attention (causal), bf16 hi/lo inputs via cp.async ============
#define LDV 136
#define FARR (128*LDV*2)
#define FLASH_SMEM (6*FARR)

__global__ __launch_bounds__(256, 1)
void flash_hmma(const __nv_bfloat16* __restrict__ Qhg, const __nv_bfloat16* __restrict__ Qlg,
                const __nv_bfloat16* __restrict__ Khg, const __nv_bfloat16* __restrict__ Klg,
                const __nv_bfloat16* __restrict__ Vhg, const __nv_bfloat16* __restrict__ Vlg,
                __nv_bfloat16* __restrict__ Oh, __nv_bfloat16* __restrict__ Ol)
{
    extern __shared__ char fsm[];
    const u32 QH = smem_u32(fsm);
    const u32 QL = QH + FARR;
    const u32 KH = QH + 2*FARR;
    const u32 KL = QH + 3*FARR;
    const u32 VH = QH + 4*FARR;
    const u32 VL = QH + 5*FARR;

    const int tid = threadIdx.x;
    const int w = tid >> 5, lane = tid & 31;
    const int qi = (int)gridDim.x - 1 - (int)blockIdx.x;   // heavy CTAs first
    const int h = blockIdx.y, b = blockIdx.z;
    const int q0 = qi * 128;
    const int R = w * 16;

    const int qrow_l = (lane & 7) + ((lane >> 3) & 1) * 8;
    const int qcol_l = (lane >> 4) * 8;
    const int krow_l = (lane & 7) + (lane >> 4) * 8;
    const int kcol_l = ((lane >> 3) & 1) * 8;
    const int vrow_l = (lane & 7) + ((lane >> 3) & 1) * 8;
    const int vcol_l = (lane >> 4) * 8;

    const int ldrow = tid >> 1;
    const int ldc0  = (tid & 1) * 64;

    // ---- load Q hi/lo via cp.async ----
    {
        const size_t gq = ((size_t)(b * S_LEN + q0 + ldrow)) * DIM + h * HD + ldc0;
        const u32 soff = (u32)(ldrow * LDV + ldc0) * 2;
        #pragma unroll
        for (int j = 0; j < 8; j++) {
            cpa16(QH + soff + j*16, Qhg + gq + j*8);
            cpa16(QL + soff + j*16, Qlg + gq + j*8);
        }
        asm volatile("cp.async.commit_group;" ::: "memory");
    }

    float S[16][4], O[16][4];
    #pragma unroll
    for (int n = 0; n < 16; n++)
        #pragma unroll
        for (int j = 0; j < 4; j++) O[n][j] = 0.0f;
    float m0 = -1e30f, m1 = -1e30f, l0 = 0.0f, l1 = 0.0f;

    #pragma unroll 1
    for (int kt = 0; kt <= qi; kt++) {
        __syncthreads();   // previous tile's ldsm complete before overwrite
        {
            const size_t gk = ((size_t)(b * S_LEN + kt * 128 + ldrow)) * DIM + h * HD + ldc0;
            const u32 soff = (u32)(ldrow * LDV + ldc0) * 2;
            #pragma unroll
            for (int j = 0; j < 8; j++) {
                cpa16(KH + soff + j*16, Khg + gk + j*8);
                cpa16(KL + soff + j*16, Klg + gk + j*8);
                cpa16(VH + soff + j*16, Vhg + gk + j*8);
                cpa16(VL + soff + j*16, Vlg + gk + j*8);
            }
            asm volatile("cp.async.commit_group;" ::: "memory");
            asm volatile("cp.async.wait_group 0;" ::: "memory");
        }
        __syncthreads();

        // ---- S = Q K^T (3-term) ----
        #pragma unroll
        for (int n = 0; n < 16; n++)
            #pragma unroll
            for (int j = 0; j < 4; j++) S[n][j] = 0.0f;

        #pragma unroll
        for (int ks = 0; ks < 8; ks++) {
            u32 qh[4], ql[4];
            const u32 qoff = (u32)((R + qrow_l) * LDV + ks * 16 + qcol_l) * 2;
            ldsm4(qh, QH + qoff);
            ldsm4(ql, QL + qoff);
            #pragma unroll
            for (int n2 = 0; n2 < 8; n2++) {
                u32 kh[4], kl[4];
                const u32 koff = (u32)((n2 * 16 + krow_l) * LDV + ks * 16 + kcol_l) * 2;
                ldsm4(kh, KH + koff);
                ldsm4(kl, KL + koff);
                mma16816(S[2*n2],     qh, kh);     mma16816(S[2*n2],     ql, kh);     mma16816(S[2*n2],     qh, kl);
                mma16816(S[2*n2 + 1], qh, kh + 2); mma16816(S[2*n2 + 1], ql, kh + 2); mma16816(S[2*n2 + 1], qh, kl + 2);
            }
        }

        if (kt == qi) {
            const int r_lo = R + (lane >> 2);
            #pragma unroll
            for (int n = 0; n < 16; n++) {
                const int c = n * 8 + (lane & 3) * 2;
                if (c     > r_lo)     S[n][0] = -1e30f;
                if (c + 1 > r_lo)     S[n][1] = -1e30f;
                if (c     > r_lo + 8) S[n][2] = -1e30f;
                if (c + 1 > r_lo + 8) S[n][3] = -1e30f;
            }
        }

        // ---- online softmax ----
        {
            float mx0 = -1e30f, mx1 = -1e30f;
            #pragma unroll
            for (int n = 0; n < 16; n++) {
                mx0 = fmaxf(mx0, fmaxf(S[n][0], S[n][1]));
                mx1 = fmaxf(mx1, fmaxf(S[n][2], S[n][3]));
            }
            mx0 = fmaxf(mx0, __shfl_xor_sync(0xffffffffu, mx0, 1));
            mx0 = fmaxf(mx0, __shfl_xor_sync(0xffffffffu, mx0, 2));
            mx1 = fmaxf(mx1, __shfl_xor_sync(0xffffffffu, mx1, 1));
            mx1 = fmaxf(mx1, __shfl_xor_sync(0xffffffffu, mx1, 2));

            const float m0n = fmaxf(m0, mx0);
            const float m1n = fmaxf(m1, mx1);
            const float f0 = __expf(m0 - m0n);
            const float f1 = __expf(m1 - m1n);

            float s0 = 0.0f, s1 = 0.0f;
            #pragma unroll
            for (int n = 0; n < 16; n++) {
                S[n][0] = __expf(S[n][0] - m0n); s0 += S[n][0];
                S[n][1] = __expf(S[n][1] - m0n); s0 += S[n][1];
                S[n][2] = __expf(S[n][2] - m1n); s1 += S[n][2];
                S[n][3] = __expf(S[n][3] - m1n); s1 += S[n][3];
            }
            s0 += __shfl_xor_sync(0xffffffffu, s0, 1);
            s0 += __shfl_xor_sync(0xffffffffu, s0, 2);
            s1 += __shfl_xor_sync(0xffffffffu, s1, 1);
            s1 += __shfl_xor_sync(0xffffffffu, s1, 2);

            l0 = l0 * f0 + s0;  l1 = l1 * f1 + s1;
            m0 = m0n;           m1 = m1n;

            #pragma unroll
            for (int n = 0; n < 16; n++) {
                O[n][0] *= f0;  O[n][1] *= f0;
                O[n][2] *= f1;  O[n][3] *= f1;
            }
        }

        // ---- O += P V (3-term; P frags from registers) ----
        #pragma unroll
        for (int ks = 0; ks < 8; ks++) {
            u32 ph[4], pl[4];
            #pragma unroll
            for (int t = 0; t < 4; t++) {
                const int n = 2*ks + (t >> 1);
                const int j0 = (t & 1) * 2;
                const float p0 = S[n][j0], p1 = S[n][j0 + 1];
                const __nv_bfloat16 h0 = __float2bfloat16_rn(p0);
                const __nv_bfloat16 h1 = __float2bfloat16_rn(p1);
                ph[t] = (u32)__bfloat16_as_ushort(h0) | ((u32)__bfloat16_as_ushort(h1) << 16);
                pl[t] = pkbf(p0 - __bfloat162float(h0), p1 - __bfloat162float(h1));
            }
            #pragma unroll
            for (int n2 = 0; n2 < 8; n2++) {
                u32 vh[4], vl[4];
                const u32 voff = (u32)((ks * 16 + vrow_l) * LDV + n2 * 16 + vcol_l) * 2;
                ldsm4t(vh, VH + voff);
                ldsm4t(vl, VL + voff);
                mma16816(O[2*n2],     ph, vh);     mma16816(O[2*n2],     pl, vh);     mma16816(O[2*n2],     ph, vl);
                mma16816(O[2*n2 + 1], ph, vh + 2); mma16816(O[2*n2 + 1], pl, vh + 2); mma16816(O[2*n2 + 1], ph, vl + 2);
            }
        }
    }

    // ---- epilogue ----
    {
        const float inv0 = 1.0f / l0;
        const float inv1 = 1.0f / l1;
        const size_t row0 = (size_t)(b * S_LEN + q0 + R + (lane >> 2));
        const size_t row1 = row0 + 8;
        const int colb = h * HD + (lane & 3) * 2;
        #pragma unroll
        for (int n = 0; n < 16; n++) {
            const int col = colb + n * 8;
            store_split(Oh, Ol, row0 * DIM + col, O[n][0] * inv0, O[n][1] * inv0);
            store_split(Oh, Ol, row1 * DIM + col, O[n][2] * inv1, O[n][3] * inv1);
        }
    }
}

extern "C" void kernel_launch(void* const* d_in, const int* in_sizes, int n_in,
                              void* d_out, int out_size)
{
    const float* x  = (const float*)d_in[0];
    const float* wq = (const float*)d_in[1];
    const float* wk = (const float*)d_in[2];
    const float* wv = (const float*)d_in[3];
    const float* wo = (const float*)d_in[4];
    const float* fc = (const float*)d_in[5];
    const float* fs = (const float*)d_in[6];
    float* out = (float*)d_out;

    __nv_bfloat16 *xh, *xl, *wqh, *wql, *wkh, *wkl, *wvh, *wvl, *woh, *wol;
    __nv_bfloat16 *qh, *ql, *kh, *kl, *vh, *vl, *ah, *al;
    cudaGetSymbolAddress((void**)&xh,  g_xh);   cudaGetSymbolAddress((void**)&xl,  g_xl);
    cudaGetSymbolAddress((void**)&wqh, g_wqh);  cudaGetSymbolAddress((void**)&wql, g_wql);
    cudaGetSymbolAddress((void**)&wkh, g_wkh);  cudaGetSymbolAddress((void**)&wkl, g_wkl);
    cudaGetSymbolAddress((void**)&wvh, g_wvh);  cudaGetSymbolAddress((void**)&wvl, g_wvl);
    cudaGetSymbolAddress((void**)&woh, g_woh);  cudaGetSymbolAddress((void**)&wol, g_wol);
    cudaGetSymbolAddress((void**)&qh,  g_qh);   cudaGetSymbolAddress((void**)&ql,  g_ql);
    cudaGetSymbolAddress((void**)&kh,  g_kh);   cudaGetSymbolAddress((void**)&kl,  g_kl);
    cudaGetSymbolAddress((void**)&vh,  g_vh);   cudaGetSymbolAddress((void**)&vl,  g_vl);
    cudaGetSymbolAddress((void**)&ah,  g_ah);   cudaGetSymbolAddress((void**)&al,  g_al);

    cudaFuncSetAttribute(gemm_qkv,  cudaFuncAttributeMaxDynamicSharedMemorySize, GEMM_SMEM);
    cudaFuncSetAttribute(gemm_out,  cudaFuncAttributeMaxDynamicSharedMemorySize, GEMM_SMEM);
    cudaFuncSetAttribute(flash_hmma, cudaFuncAttributeMaxDynamicSharedMemorySize, FLASH_SMEM);

    const int splitBlocks = (DIM * DIM / 4) / 256;
    split_bf16<<<splitBlocks, 256>>>(x,  xh,  xl);
    split_bf16<<<splitBlocks, 256>>>(wq, wqh, wql);
    split_bf16<<<splitBlocks, 256>>>(wk, wkh, wkl);
    split_bf16<<<splitBlocks, 256>>>(wv, wvh, wvl);
    split_bf16<<<splitBlocks, 256>>>(wo, woh, wol);

    dim3 gq(96, 32);
    gemm_qkv<<<gq, 256, GEMM_SMEM>>>(xh, xl, wqh, wql, wkh, wkl, wvh, wvl,
                                     qh, ql, kh, kl, vh, vl, fc, fs);

    dim3 ga(S_LEN / 128, NH, BATCH);
    flash_hmma<<<ga, 256, FLASH_SMEM>>>(qh, ql, kh, kl, vh, vl, ah, al);

    dim3 gt(32, 32);
    gemm_out<<<gt, 256, GEMM_SMEM>>>(ah, al, woh, wol, out);
}